// round 4
// baseline (speedup 1.0000x reference)
#include <cuda_runtime.h>

#define B_ 2
#define N_ 1024
#define D_ 128
#define H_ 64

// Scratch (no allocations allowed): intermediate projections.
__device__ float g_ai[B_ * N_ * H_];    // [b][n][h]
__device__ float g_ajbT[B_ * H_ * N_];  // [b][h][n]  (aj + b1, transposed)

// ---------------------------------------------------------------------------
// Pass 1: ai = E @ Wi^T ; ajbT = (E @ Wj^T + b1) transposed to [h][n].
// Block = 256 threads handles 16 rows of E. Grid = 2048/16 = 128 blocks.
// ---------------------------------------------------------------------------
__global__ __launch_bounds__(256) void pass1_kernel(
    const float* __restrict__ E, const float* __restrict__ W1,
    const float* __restrict__ b1)
{
    __shared__ float Esh[16][32];
    __shared__ float Wc[32][128];

    const int tid = threadIdx.x;
    const int r = tid >> 4;
    const int ob = (tid & 15) * 8;
    const int row0 = blockIdx.x * 16;

    float acc[8];
#pragma unroll
    for (int k = 0; k < 8; k++) acc[k] = 0.f;

    for (int dc = 0; dc < D_; dc += 32) {
        __syncthreads();
#pragma unroll
        for (int k = tid; k < 16 * 32; k += 256) {
            int rr = k >> 5, dd = k & 31;
            Esh[rr][dd] = E[(row0 + rr) * D_ + dc + dd];
        }
#pragma unroll
        for (int k = tid; k < 32 * 128; k += 256) {
            int dd = k >> 7, o = k & 127;
            float v = (o < H_) ? W1[o * (2 * D_) + dc + dd]
                               : W1[(o - H_) * (2 * D_) + D_ + dc + dd];
            Wc[dd][o] = v;
        }
        __syncthreads();
#pragma unroll
        for (int dd = 0; dd < 32; dd++) {
            const float e = Esh[r][dd];
            const float4 w0 = *(const float4*)&Wc[dd][ob];
            const float4 w1v = *(const float4*)&Wc[dd][ob + 4];
            acc[0] += e * w0.x;  acc[1] += e * w0.y;
            acc[2] += e * w0.z;  acc[3] += e * w0.w;
            acc[4] += e * w1v.x; acc[5] += e * w1v.y;
            acc[6] += e * w1v.z; acc[7] += e * w1v.w;
        }
    }

    const int row = row0 + r;            // row = b*N + n
    if (ob < H_) {
#pragma unroll
        for (int k = 0; k < 8; k++) g_ai[row * H_ + ob + k] = acc[k];
    } else {
        const int b = row >> 10;
        const int n = row & (N_ - 1);
        const int h0 = ob - H_;
#pragma unroll
        for (int k = 0; k < 8; k++)
            g_ajbT[(b * H_ + h0 + k) * N_ + n] = acc[k] + b1[h0 + k];
    }
}

// ---------------------------------------------------------------------------
// Pass 2: fused edge weights + mask + softmax + write.
// Grid = B * N/8 = 256 blocks, 8 warps/block; warp w owns row i = i_base + w.
// Lane l owns j = t*128 + l*4 .. +3 for each of 8 j-tiles. In-register softmax.
// visited is int32 (harness materializes jax bool as int32).
// ---------------------------------------------------------------------------
__global__ __launch_bounds__(256) void pass2_kernel(
    const int* __restrict__ visited,
    const float* __restrict__ W2, const float* __restrict__ b2,
    float* __restrict__ out)
{
    __shared__ float ajb[H_][128];          // 32 KB
    __shared__ float ai_sh[8][H_];          // 2 KB
    __shared__ float w2_sh[H_];
    __shared__ int vis_sh[N_];              // 4 KB

    const int tid = threadIdx.x;
    const int w = tid >> 5, lane = tid & 31;
    const int b = blockIdx.x >> 7;
    const int i_base = (blockIdx.x & 127) * 8;
    const int i = i_base + w;

#pragma unroll
    for (int k = tid; k < 8 * H_; k += 256)
        ((float*)ai_sh)[k] = g_ai[(b * N_ + i_base) * H_ + k];
    if (tid < H_) w2_sh[tid] = W2[tid];
#pragma unroll
    for (int k = tid; k < N_; k += 256) vis_sh[k] = visited[b * N_ + k];

    float acc[8][4];

#pragma unroll
    for (int t = 0; t < 8; t++) {
        __syncthreads();
#pragma unroll
        for (int k = tid; k < H_ * 32; k += 256) {
            int h = k >> 5, c4 = k & 31;
            *(float4*)&ajb[h][c4 * 4] =
                *(const float4*)&g_ajbT[(b * H_ + h) * N_ + t * 128 + c4 * 4];
        }
        __syncthreads();

        float s0 = 0.f, s1 = 0.f, s2 = 0.f, s3 = 0.f;
#pragma unroll 8
        for (int h = 0; h < H_; h++) {
            const float a = ai_sh[w][h];     // warp broadcast
            const float wv = w2_sh[h];       // warp broadcast
            const float4 v = *(const float4*)&ajb[h][lane * 4];
            s0 += fmaxf(a + v.x, 0.f) * wv;
            s1 += fmaxf(a + v.y, 0.f) * wv;
            s2 += fmaxf(a + v.z, 0.f) * wv;
            s3 += fmaxf(a + v.w, 0.f) * wv;
        }
        acc[t][0] = s0; acc[t][1] = s1; acc[t][2] = s2; acc[t][3] = s3;
    }

    // ---- mask + softmax (in registers, warp-wide) ----
    const float bb = b2[0];
    const bool vi = vis_sh[i] != 0;
    float m = -3.4e38f;
#pragma unroll
    for (int t = 0; t < 8; t++)
#pragma unroll
        for (int k = 0; k < 4; k++) {
            const int j = t * 128 + lane * 4 + k;
            float e = (vi || (vis_sh[j] != 0)) ? -1.0e9f : (acc[t][k] + bb);
            acc[t][k] = e;
            m = fmaxf(m, e);
        }
#pragma unroll
    for (int o = 16; o > 0; o >>= 1)
        m = fmaxf(m, __shfl_xor_sync(0xffffffffu, m, o));

    float sum = 0.f;
#pragma unroll
    for (int t = 0; t < 8; t++)
#pragma unroll
        for (int k = 0; k < 4; k++) {
            const float p = __expf(acc[t][k] - m);
            acc[t][k] = p;
            sum += p;
        }
#pragma unroll
    for (int o = 16; o > 0; o >>= 1)
        sum += __shfl_xor_sync(0xffffffffu, sum, o);

    const float inv = 1.f / sum;
    float* orow = out + (size_t)(b * N_ + i) * N_;
#pragma unroll
    for (int t = 0; t < 8; t++) {
        float4 o4 = make_float4(acc[t][0] * inv, acc[t][1] * inv,
                                acc[t][2] * inv, acc[t][3] * inv);
        *(float4*)&orow[t * 128 + lane * 4] = o4;
    }
}

extern "C" void kernel_launch(void* const* d_in, const int* in_sizes, int n_in,
                              void* d_out, int out_size) {
    const float* E  = (const float*)d_in[0];
    const int* vis  = (const int*)d_in[1];   // jax bool -> int32 in harness
    // d_in[2] = remaining_capacity: unused by the reference.
    const float* W1 = (const float*)d_in[3];
    const float* b1 = (const float*)d_in[4];
    const float* W2 = (const float*)d_in[5];
    const float* b2 = (const float*)d_in[6];
    float* out      = (float*)d_out;

    pass1_kernel<<<128, 256>>>(E, W1, b1);
    pass2_kernel<<<256, 256>>>(vis, W2, b2, out);
}

// round 5
// speedup vs baseline: 1.2983x; 1.2983x over previous
#include <cuda_runtime.h>

#define B_ 2
#define N_ 1024
#define D_ 128
#define H_ 64

// Scratch (no allocations allowed): intermediate projections.
__device__ float g_ai[B_ * N_ * H_];    // [b][n][h]
__device__ float g_ajbT[B_ * H_ * N_];  // [b][h][n]  (aj + b1, transposed)

// ---------------------------------------------------------------------------
// Pass 1: ai = E @ Wi^T ; ajbT = (E @ Wj^T + b1) transposed to [h][n].
// Block = 256 threads, 16 rows of E. Grid = 128.
// W staging: coalesced LDG (consecutive lanes -> consecutive d), padded SMEM
// (132 stride: 4-way STS conflicts max, rows stay 16B-aligned for LDS.128).
// ---------------------------------------------------------------------------
__global__ __launch_bounds__(256) void pass1_kernel(
    const float* __restrict__ E, const float* __restrict__ W1,
    const float* __restrict__ b1)
{
    __shared__ float Esh[16][32];
    __shared__ float Wc[32][132];

    const int tid = threadIdx.x;
    const int r = tid >> 4;
    const int ob = (tid & 15) * 8;
    const int row0 = blockIdx.x * 16;

    float acc[8];
#pragma unroll
    for (int k = 0; k < 8; k++) acc[k] = 0.f;

    for (int dc = 0; dc < D_; dc += 32) {
        __syncthreads();
#pragma unroll
        for (int k = tid; k < 16 * 32; k += 256) {
            int rr = k >> 5, dd = k & 31;
            Esh[rr][dd] = E[(row0 + rr) * D_ + dc + dd];
        }
        // Coalesced: consecutive lanes -> consecutive dd within one W1 row.
#pragma unroll
        for (int k = tid; k < 32 * 128; k += 256) {
            int o = k >> 5, dd = k & 31;
            float v = (o < H_) ? W1[o * (2 * D_) + dc + dd]
                               : W1[(o - H_) * (2 * D_) + D_ + dc + dd];
            Wc[dd][o] = v;
        }
        __syncthreads();
#pragma unroll
        for (int dd = 0; dd < 32; dd++) {
            const float e = Esh[r][dd];
            const float4 w0 = *(const float4*)&Wc[dd][ob];
            const float4 w1v = *(const float4*)&Wc[dd][ob + 4];
            acc[0] += e * w0.x;  acc[1] += e * w0.y;
            acc[2] += e * w0.z;  acc[3] += e * w0.w;
            acc[4] += e * w1v.x; acc[5] += e * w1v.y;
            acc[6] += e * w1v.z; acc[7] += e * w1v.w;
        }
    }

    const int row = row0 + r;            // row = b*N + n
    if (ob < H_) {
#pragma unroll
        for (int k = 0; k < 8; k++) g_ai[row * H_ + ob + k] = acc[k];
    } else {
        const int b = row >> 10;
        const int n = row & (N_ - 1);
        const int h0 = ob - H_;
#pragma unroll
        for (int k = 0; k < 8; k++)
            g_ajbT[(b * H_ + h0 + k) * N_ + n] = acc[k] + b1[h0 + k];
    }
}

// ---------------------------------------------------------------------------
// Pass 2: fused edge weights + mask + softmax + write.
// Grid = B * N/16 = 128 blocks, 256 threads = 8 warps. Warp w owns TWO rows
// i0 = i_base + 2w, i0+1: each LDS.128 of ajb feeds both rows (halves the
// crossbar traffic per unit work). (ai0, ai1, w2) packed as one float4
// broadcast per h. Full rows kept in registers for in-register softmax.
// ---------------------------------------------------------------------------
__global__ __launch_bounds__(256) void pass2_kernel(
    const int* __restrict__ visited,
    const float* __restrict__ W2, const float* __restrict__ b2,
    float* __restrict__ out)
{
    __shared__ float ajb[H_][128];          // 32 KB
    __shared__ float4 comb[8][H_];          // 8 KB: (ai_row0, ai_row1, w2, 0)
    __shared__ int vis_sh[N_];              // 4 KB

    const int tid = threadIdx.x;
    const int w = tid >> 5, lane = tid & 31;
    const int b = blockIdx.x >> 6;
    const int i_base = (blockIdx.x & 63) * 16;
    const int i0 = i_base + 2 * w;

#pragma unroll
    for (int k = tid; k < 8 * H_; k += 256) {
        int wi = k >> 6, h = k & 63;
        int ii = i_base + 2 * wi;
        comb[wi][h] = make_float4(g_ai[(b * N_ + ii) * H_ + h],
                                  g_ai[(b * N_ + ii + 1) * H_ + h],
                                  W2[h], 0.f);
    }
#pragma unroll
    for (int k = tid; k < N_; k += 256) vis_sh[k] = visited[b * N_ + k];

    float a0[8][4], a1[8][4];

#pragma unroll
    for (int t = 0; t < 8; t++) {
        __syncthreads();
#pragma unroll
        for (int k = tid; k < H_ * 32; k += 256) {
            int h = k >> 5, c4 = k & 31;
            *(float4*)&ajb[h][c4 * 4] =
                *(const float4*)&g_ajbT[(b * H_ + h) * N_ + t * 128 + c4 * 4];
        }
        __syncthreads();

        float s00 = 0.f, s01 = 0.f, s02 = 0.f, s03 = 0.f;
        float s10 = 0.f, s11 = 0.f, s12 = 0.f, s13 = 0.f;
#pragma unroll 8
        for (int h = 0; h < H_; h++) {
            const float4 c = comb[w][h];                 // 16B broadcast
            const float4 v = *(const float4*)&ajb[h][lane * 4];
            s00 += fmaxf(c.x + v.x, 0.f) * c.z;
            s01 += fmaxf(c.x + v.y, 0.f) * c.z;
            s02 += fmaxf(c.x + v.z, 0.f) * c.z;
            s03 += fmaxf(c.x + v.w, 0.f) * c.z;
            s10 += fmaxf(c.y + v.x, 0.f) * c.z;
            s11 += fmaxf(c.y + v.y, 0.f) * c.z;
            s12 += fmaxf(c.y + v.z, 0.f) * c.z;
            s13 += fmaxf(c.y + v.w, 0.f) * c.z;
        }
        a0[t][0] = s00; a0[t][1] = s01; a0[t][2] = s02; a0[t][3] = s03;
        a1[t][0] = s10; a1[t][1] = s11; a1[t][2] = s12; a1[t][3] = s13;
    }

    // ---- mask + softmax for both rows (in registers, warp-wide) ----
    const float bb = b2[0];
    const bool vi0 = vis_sh[i0] != 0;
    const bool vi1 = vis_sh[i0 + 1] != 0;
    float m0 = -3.4e38f, m1 = -3.4e38f;
#pragma unroll
    for (int t = 0; t < 8; t++)
#pragma unroll
        for (int k = 0; k < 4; k++) {
            const int j = t * 128 + lane * 4 + k;
            const bool vj = vis_sh[j] != 0;
            float e0 = (vi0 || vj) ? -1.0e9f : (a0[t][k] + bb);
            float e1 = (vi1 || vj) ? -1.0e9f : (a1[t][k] + bb);
            a0[t][k] = e0; a1[t][k] = e1;
            m0 = fmaxf(m0, e0); m1 = fmaxf(m1, e1);
        }
#pragma unroll
    for (int o = 16; o > 0; o >>= 1) {
        m0 = fmaxf(m0, __shfl_xor_sync(0xffffffffu, m0, o));
        m1 = fmaxf(m1, __shfl_xor_sync(0xffffffffu, m1, o));
    }

    float sum0 = 0.f, sum1 = 0.f;
#pragma unroll
    for (int t = 0; t < 8; t++)
#pragma unroll
        for (int k = 0; k < 4; k++) {
            const float p0 = __expf(a0[t][k] - m0);
            const float p1 = __expf(a1[t][k] - m1);
            a0[t][k] = p0; a1[t][k] = p1;
            sum0 += p0; sum1 += p1;
        }
#pragma unroll
    for (int o = 16; o > 0; o >>= 1) {
        sum0 += __shfl_xor_sync(0xffffffffu, sum0, o);
        sum1 += __shfl_xor_sync(0xffffffffu, sum1, o);
    }

    const float inv0 = 1.f / sum0;
    const float inv1 = 1.f / sum1;
    float* orow0 = out + (size_t)(b * N_ + i0) * N_;
    float* orow1 = orow0 + N_;
#pragma unroll
    for (int t = 0; t < 8; t++) {
        *(float4*)&orow0[t * 128 + lane * 4] =
            make_float4(a0[t][0] * inv0, a0[t][1] * inv0,
                        a0[t][2] * inv0, a0[t][3] * inv0);
        *(float4*)&orow1[t * 128 + lane * 4] =
            make_float4(a1[t][0] * inv1, a1[t][1] * inv1,
                        a1[t][2] * inv1, a1[t][3] * inv1);
    }
}

extern "C" void kernel_launch(void* const* d_in, const int* in_sizes, int n_in,
                              void* d_out, int out_size) {
    const float* E  = (const float*)d_in[0];
    const int* vis  = (const int*)d_in[1];   // jax bool -> int32 in harness
    // d_in[2] = remaining_capacity: unused by the reference.
    const float* W1 = (const float*)d_in[3];
    const float* b1 = (const float*)d_in[4];
    const float* W2 = (const float*)d_in[5];
    const float* b2 = (const float*)d_in[6];
    float* out      = (float*)d_out;

    pass1_kernel<<<128, 256>>>(E, W1, b1);
    pass2_kernel<<<128, 256>>>(vis, W2, b2, out);
}